// round 16
// baseline (speedup 1.0000x reference)
#include <cuda_runtime.h>
#include <cuda_fp16.h>

// Problem constants (fixed by reference)
#define BB 2
#define TT 4096
#define CC 128
#define HH 8
#define DD 16
#define LOG2E 1.4426950408889634f

typedef unsigned int u32;
typedef unsigned short u16;
typedef unsigned long long ull;

__device__ __forceinline__ float ex2(float x) {
    float r; asm("ex2.approx.f32 %0, %1;" : "=f"(r) : "f"(x)); return r;
}
// pack two fp32 -> f16x2 (lo = first arg in low half)
__device__ __forceinline__ u32 pack_f16(float lo, float hi) {
    u32 r; asm("cvt.rn.f16x2.f32 %0, %1, %2;" : "=r"(r) : "f"(hi), "f"(lo)); return r;
}

#define MMA_F16(c0,c1,c2,c3,a0,a1,a2,a3,b0,b1)                          \
    asm("mma.sync.aligned.m16n8k16.row.col.f32.f16.f16.f32 "            \
        "{%0,%1,%2,%3}, {%4,%5,%6,%7}, {%8,%9}, {%0,%1,%2,%3};"         \
        : "+f"(c0), "+f"(c1), "+f"(c2), "+f"(c3)                        \
        : "r"(a0), "r"(a1), "r"(a2), "r"(a3), "r"(b0), "r"(b1))

// Scratch (device globals — no allocation allowed in kernel_launch)
__device__ u16  g_x16[BB * TT * CC];      // fp16 copy of x
__device__ u16  g_qh[BB * HH * TT * DD];  // fp16 [b][h][t][d], pre-scaled by 0.25*log2e
__device__ u16  g_kh[BB * HH * TT * DD];  // fp16 [b][h][t][d]
__device__ u16  g_vt[BB * HH * DD * TT];  // fp16 [b][h][d][t]  (transposed!)
__device__ u16  g_att16[BB * TT * CC];    // fp16 [b][t][h*16+d]

// ---------------------------------------------------------------------------
// Kernel 0: convert x to fp16 (1M elems, 4 per thread).
// ---------------------------------------------------------------------------
__global__ void __launch_bounds__(256)
cvt_x_kernel(const float* __restrict__ x) {
    const int i = blockIdx.x * 256 + threadIdx.x;     // 0..262143
    const float4 v = ((const float4*)x)[i];
    uint2 p;
    p.x = pack_f16(v.x, v.y);
    p.y = pack_f16(v.z, v.w);
    ((uint2*)g_x16)[i] = p;
}

// ---------------------------------------------------------------------------
// Kernel 1: QKV projection via fp16 MMA (fp32 accum).  (verified R13)
// ---------------------------------------------------------------------------
__global__ void __launch_bounds__(128)
qkv_mma_kernel(const float* __restrict__ Wq,
               const float* __restrict__ Wk,
               const float* __restrict__ Wv) {
    __shared__ u32 ws[128 * 68];            // 128 rows x 136 halves (34816 B)
    const int rowbase = blockIdx.x * 64;
    const int w = blockIdx.y;
    const int tid = threadIdx.x;
    const int warp = tid >> 5;
    const int lane = tid & 31;
    const int gr = lane >> 2;
    const int t4 = lane & 3;

    const float* W = (w == 0) ? Wq : (w == 1) ? Wk : Wv;

    {
        const float4* wr = (const float4*)(W + (size_t)tid * CC);
        u32* sr = ws + tid * 68;
#pragma unroll 8
        for (int c4 = 0; c4 < 32; c4++) {
            const float4 v = wr[c4];
            sr[2 * c4]     = pack_f16(v.x, v.y);
            sr[2 * c4 + 1] = pack_f16(v.z, v.w);
        }
    }
    __syncthreads();

    const int r0 = rowbase + warp * 16 + gr;   // A row for c0/c1
    const int r1 = r0 + 8;                     // A row for c2/c3
    const u32* x0 = (const u32*)g_x16 + (size_t)r0 * (CC / 2);
    const u32* x1 = (const u32*)g_x16 + (size_t)r1 * (CC / 2);

    float c[16][4];
#pragma unroll
    for (int nt = 0; nt < 16; nt++) {
        c[nt][0] = 0.f; c[nt][1] = 0.f; c[nt][2] = 0.f; c[nt][3] = 0.f;
    }

#pragma unroll
    for (int ks = 0; ks < 8; ks++) {
        const u32 a0 = x0[ks * 8 + t4];
        const u32 a1 = x1[ks * 8 + t4];
        const u32 a2 = x0[ks * 8 + t4 + 4];
        const u32 a3 = x1[ks * 8 + t4 + 4];
#pragma unroll
        for (int nt = 0; nt < 16; nt++) {
            const u32* br = ws + (nt * 8 + gr) * 68 + ks * 8;
            MMA_F16(c[nt][0], c[nt][1], c[nt][2], c[nt][3],
                    a0, a1, a2, a3, br[t4], br[t4 + 4]);
        }
    }

    const float scale = (w == 0) ? 0.25f * LOG2E : 1.0f;
    const int b = r0 >> 12;                    // rowbase%64==0, so b same for r0/r1
    const int t0 = r0 & (TT - 1);
    const int t1 = r1 & (TT - 1);

#pragma unroll
    for (int nt = 0; nt < 16; nt++) {
        const int n = nt * 8 + 2 * t4;         // output column (even)
        const int h = n >> 4;
        const int d = n & 15;
        const u32 p0 = pack_f16(c[nt][0] * scale, c[nt][1] * scale);
        const u32 p1 = pack_f16(c[nt][2] * scale, c[nt][3] * scale);
        if (w == 0) {
            *(u32*)(g_qh + ((size_t)((b * HH + h) * TT + t0) * DD + d)) = p0;
            *(u32*)(g_qh + ((size_t)((b * HH + h) * TT + t1) * DD + d)) = p1;
        } else if (w == 1) {
            *(u32*)(g_kh + ((size_t)((b * HH + h) * TT + t0) * DD + d)) = p0;
            *(u32*)(g_kh + ((size_t)((b * HH + h) * TT + t1) * DD + d)) = p1;
        } else {
            const size_t vb = (size_t)(b * HH + h) * DD;
            g_vt[(vb + d) * TT + t0]     = (u16)(p0 & 0xffff);
            g_vt[(vb + d + 1) * TT + t0] = (u16)(p0 >> 16);
            g_vt[(vb + d) * TT + t1]     = (u16)(p1 & 0xffff);
            g_vt[(vb + d + 1) * TT + t1] = (u16)(p1 >> 16);
        }
    }
}

// ---------------------------------------------------------------------------
// Kernel 2: causal flash attention, fp16 mma (f32 accum).
// 32 queries per warp (two m16 A-tiles, rows +0/+8 and +16/+24) so every
// K / V B-fragment load feeds TWO MMAs. Block = 128 queries, 4 warps, no smem.
// P packed to fp16 immediately after ex2 to bound register pressure.
// Per-row arithmetic identical to the verified 16-q/warp version.
// ---------------------------------------------------------------------------
__global__ void __launch_bounds__(128)
attn_kernel() {
    const int Q0 = ((gridDim.x - 1) - blockIdx.x) * 128;  // heaviest first
    const int bh = blockIdx.y;                            // b*HH + h
    const int warp = threadIdx.x >> 5;
    const int lane = threadIdx.x & 31;
    const int gr = lane >> 2;
    const int t4 = lane & 3;

    const u16* qbase_p = g_qh + (size_t)bh * TT * DD;
    const u16* kbase   = g_kh + (size_t)bh * TT * DD;
    const u16* vbase   = g_vt + (size_t)bh * DD * TT;

    const int qbase = Q0 + warp * 32;          // warp's first query
    const int qg0 = qbase + gr;                // tile0 rows (c0/c1)
    const int qg1 = qbase + 8 + gr;            // tile0 rows (c2/c3)
    const int qg2 = qbase + 16 + gr;           // tile1 rows (c0/c1)
    const int qg3 = qbase + 24 + gr;           // tile1 rows (c2/c3)

    // A-fragments for both q-tiles
    const u32* qr0 = (const u32*)(qbase_p + (size_t)qg0 * DD);
    const u32* qr1 = (const u32*)(qbase_p + (size_t)qg1 * DD);
    const u32* qr2 = (const u32*)(qbase_p + (size_t)qg2 * DD);
    const u32* qr3 = (const u32*)(qbase_p + (size_t)qg3 * DD);
    const u32 a0 = qr0[t4], a2 = qr0[t4 + 4];
    const u32 a1 = qr1[t4], a3 = qr1[t4 + 4];
    const u32 a4 = qr2[t4], a6 = qr2[t4 + 4];
    const u32 a5 = qr3[t4], a7 = qr3[t4 + 4];

    float o0[4] = {0.f,0.f,0.f,0.f};   // tile0 dims 0..7
    float o1[4] = {0.f,0.f,0.f,0.f};   // tile0 dims 8..15
    float o2[4] = {0.f,0.f,0.f,0.f};   // tile1 dims 0..7
    float o3[4] = {0.f,0.f,0.f,0.f};   // tile1 dims 8..15
    float lp0 = 0.f, lp1 = 0.f, lp2 = 0.f, lp3 = 0.f;

    const int ktmax = (qbase + 31) >> 6;

    for (int kt = 0; kt <= ktmax; kt++) {
        const int kbase_j = kt * 64;
        const bool d0 = (kbase_j + 63 > qbase);        // tile0 needs masking
        const bool d1 = (kbase_j + 63 > qbase + 16);   // tile1 needs masking

        u32 pA[8], pB[8], qA[8], qB[8];    // packed P A-frags for both tiles

        // ---- S = Q K^T over 64 keys; exp2, mask, pack ----
#pragma unroll
        for (int nt = 0; nt < 8; nt++) {
            const int key = kbase_j + nt * 8 + gr;
            const u32* kr = (const u32*)(kbase + (size_t)key * DD);
            const u32 b0 = kr[t4], b1 = kr[t4 + 4];

            float c0 = 0.f, c1 = 0.f, c2 = 0.f, c3 = 0.f;
            MMA_F16(c0, c1, c2, c3, a0, a1, a2, a3, b0, b1);
            float c4 = 0.f, c5 = 0.f, c6 = 0.f, c7 = 0.f;
            MMA_F16(c4, c5, c6, c7, a4, a5, a6, a7, b0, b1);

            const int j0 = kbase_j + nt * 8 + 2 * t4;
            float e0 = ex2(c0), e1 = ex2(c1), e2 = ex2(c2), e3 = ex2(c3);
            float e4 = ex2(c4), e5 = ex2(c5), e6 = ex2(c6), e7 = ex2(c7);
            if (d0) {
                if (j0 > qg0)     e0 = 0.f;
                if (j0 + 1 > qg0) e1 = 0.f;
                if (j0 > qg1)     e2 = 0.f;
                if (j0 + 1 > qg1) e3 = 0.f;
            }
            if (d1) {
                if (j0 > qg2)     e4 = 0.f;
                if (j0 + 1 > qg2) e5 = 0.f;
                if (j0 > qg3)     e6 = 0.f;
                if (j0 + 1 > qg3) e7 = 0.f;
            }
            lp0 += e0 + e1;  lp1 += e2 + e3;
            lp2 += e4 + e5;  lp3 += e6 + e7;
            pA[nt] = pack_f16(e0, e1);  pB[nt] = pack_f16(e2, e3);
            qA[nt] = pack_f16(e4, e5);  qB[nt] = pack_f16(e6, e7);
        }

        // ---- O += P V : shared V B-frags feed both tiles ----
#pragma unroll
        for (int ks = 0; ks < 4; ks++) {
            const u32 pa0 = pA[2 * ks],     pa1 = pB[2 * ks];
            const u32 pa2 = pA[2 * ks + 1], pa3 = pB[2 * ks + 1];
            const u32 qa0 = qA[2 * ks],     qa1 = qB[2 * ks];
            const u32 qa2 = qA[2 * ks + 1], qa3 = qB[2 * ks + 1];
            {   // output dims 0..7 : Vt row d = gr
                const u32* vr = (const u32*)(vbase + (size_t)gr * TT + kbase_j + ks * 16);
                const u32 vb0 = vr[t4], vb1 = vr[t4 + 4];
                MMA_F16(o0[0], o0[1], o0[2], o0[3], pa0, pa1, pa2, pa3, vb0, vb1);
                MMA_F16(o2[0], o2[1], o2[2], o2[3], qa0, qa1, qa2, qa3, vb0, vb1);
            }
            {   // output dims 8..15 : Vt row d = 8+gr
                const u32* vr = (const u32*)(vbase + (size_t)(8 + gr) * TT + kbase_j + ks * 16);
                const u32 vb0 = vr[t4], vb1 = vr[t4 + 4];
                MMA_F16(o1[0], o1[1], o1[2], o1[3], pa0, pa1, pa2, pa3, vb0, vb1);
                MMA_F16(o3[0], o3[1], o3[2], o3[3], qa0, qa1, qa2, qa3, vb0, vb1);
            }
        }
    }

    // row sums across the quad
    lp0 += __shfl_xor_sync(0xffffffffu, lp0, 1);
    lp0 += __shfl_xor_sync(0xffffffffu, lp0, 2);
    lp1 += __shfl_xor_sync(0xffffffffu, lp1, 1);
    lp1 += __shfl_xor_sync(0xffffffffu, lp1, 2);
    lp2 += __shfl_xor_sync(0xffffffffu, lp2, 1);
    lp2 += __shfl_xor_sync(0xffffffffu, lp2, 2);
    lp3 += __shfl_xor_sync(0xffffffffu, lp3, 1);
    lp3 += __shfl_xor_sync(0xffffffffu, lp3, 2);
    const float inv0 = 1.f / lp0;
    const float inv1 = 1.f / lp1;
    const float inv2 = 1.f / lp2;
    const float inv3 = 1.f / lp3;

    const int b = bh / HH, h = bh % HH;
    u16* ar0 = g_att16 + ((size_t)(b * TT + qg0)) * CC + h * DD;
    u16* ar1 = g_att16 + ((size_t)(b * TT + qg1)) * CC + h * DD;
    u16* ar2 = g_att16 + ((size_t)(b * TT + qg2)) * CC + h * DD;
    u16* ar3 = g_att16 + ((size_t)(b * TT + qg3)) * CC + h * DD;
    *(u32*)(ar0 + 2 * t4)     = pack_f16(o0[0] * inv0, o0[1] * inv0);
    *(u32*)(ar0 + 8 + 2 * t4) = pack_f16(o1[0] * inv0, o1[1] * inv0);
    *(u32*)(ar1 + 2 * t4)     = pack_f16(o0[2] * inv1, o0[3] * inv1);
    *(u32*)(ar1 + 8 + 2 * t4) = pack_f16(o1[2] * inv1, o1[3] * inv1);
    *(u32*)(ar2 + 2 * t4)     = pack_f16(o2[0] * inv2, o2[1] * inv2);
    *(u32*)(ar2 + 8 + 2 * t4) = pack_f16(o3[0] * inv2, o3[1] * inv2);
    *(u32*)(ar3 + 2 * t4)     = pack_f16(o2[2] * inv3, o2[3] * inv3);
    *(u32*)(ar3 + 8 + 2 * t4) = pack_f16(o3[2] * inv3, o3[3] * inv3);
}

// ---------------------------------------------------------------------------
// Kernel 3: output projection via fp16 MMA (fp32 accum + fp32 bias). (R13)
// ---------------------------------------------------------------------------
__global__ void __launch_bounds__(128)
out_proj_mma_kernel(const float* __restrict__ Wp,
                    const float* __restrict__ bp,
                    float* __restrict__ out) {
    __shared__ u32 ws[128 * 68];
    const int rowbase = blockIdx.x * 64;
    const int tid = threadIdx.x;
    const int warp = tid >> 5;
    const int lane = tid & 31;
    const int gr = lane >> 2;
    const int t4 = lane & 3;

    {
        const float4* wr = (const float4*)(Wp + (size_t)tid * CC);
        u32* sr = ws + tid * 68;
#pragma unroll 8
        for (int c4 = 0; c4 < 32; c4++) {
            const float4 v = wr[c4];
            sr[2 * c4]     = pack_f16(v.x, v.y);
            sr[2 * c4 + 1] = pack_f16(v.z, v.w);
        }
    }
    __syncthreads();

    const int r0 = rowbase + warp * 16 + gr;
    const int r1 = r0 + 8;
    const u32* x0 = (const u32*)g_att16 + (size_t)r0 * (CC / 2);
    const u32* x1 = (const u32*)g_att16 + (size_t)r1 * (CC / 2);

    float c[16][4];
#pragma unroll
    for (int nt = 0; nt < 16; nt++) {
        c[nt][0] = 0.f; c[nt][1] = 0.f; c[nt][2] = 0.f; c[nt][3] = 0.f;
    }

#pragma unroll
    for (int ks = 0; ks < 8; ks++) {
        const u32 a0 = x0[ks * 8 + t4];
        const u32 a1 = x1[ks * 8 + t4];
        const u32 a2 = x0[ks * 8 + t4 + 4];
        const u32 a3 = x1[ks * 8 + t4 + 4];
#pragma unroll
        for (int nt = 0; nt < 16; nt++) {
            const u32* br = ws + (nt * 8 + gr) * 68 + ks * 8;
            MMA_F16(c[nt][0], c[nt][1], c[nt][2], c[nt][3],
                    a0, a1, a2, a3, br[t4], br[t4 + 4]);
        }
    }

#pragma unroll
    for (int nt = 0; nt < 16; nt++) {
        const int n = nt * 8 + 2 * t4;         // output column (even)
        const float2 bb = *(const float2*)(bp + n);
        float2 r;
        r.x = c[nt][0] + bb.x; r.y = c[nt][1] + bb.y;
        *(float2*)(out + (size_t)r0 * CC + n) = r;
        r.x = c[nt][2] + bb.x; r.y = c[nt][3] + bb.y;
        *(float2*)(out + (size_t)r1 * CC + n) = r;
    }
}

// ---------------------------------------------------------------------------
// Launch.  Input order (metadata / setup_inputs dict): x, Wk, Wq, Wv, Wp, bp
// ---------------------------------------------------------------------------
extern "C" void kernel_launch(void* const* d_in, const int* in_sizes, int n_in,
                              void* d_out, int out_size) {
    const float* x  = (const float*)d_in[0];
    const float* Wk = (const float*)d_in[1];
    const float* Wq = (const float*)d_in[2];
    const float* Wv = (const float*)d_in[3];
    const float* Wp = (const float*)d_in[4];
    const float* bp = (const float*)d_in[5];
    float* out = (float*)d_out;

    cvt_x_kernel<<<(BB * TT * CC) / 1024, 256>>>(x);

    dim3 qkv_grid((BB * TT) / 64, 3);
    qkv_mma_kernel<<<qkv_grid, 128>>>(Wq, Wk, Wv);

    dim3 attn_grid(TT / 128, BB * HH);
    attn_kernel<<<attn_grid, 128>>>();

    out_proj_mma_kernel<<<(BB * TT) / 64, 128>>>(Wp, bp, out);
}